// round 16
// baseline (speedup 1.0000x reference)
#include <cuda_runtime.h>
#include <cuda_bf16.h>
#include <cuda_fp16.h>
#include <math.h>
#include <stdint.h>

#define SEQ   2048
#define EMB   1024
#define NH    16
#define HD    64
#define NB    2
#define MROWS (NB*SEQ)   // 4096
#define NIT   (EMB/32)   // proj k-chunks of 32
#define QTILE 64
#define KTILE 64
#define ATHREADS 128

// ---------------- static device scratch (allocation-free) ------------------
__device__ __half g_Ah[3][MROWS*EMB];          // activations single fp16 [m][k]
__device__ __half g_Wh[3][EMB*EMB];            // W^T single fp16 [n][k]

__device__ __half g_Qh[MROWS*EMB];             // Q (x0.125*log2e) single fp16
__device__ __half g_Kh[MROWS*EMB];             // K single fp16 [kk][d]
__device__ __half g_Vh[MROWS*EMB];             // V single fp16 [kk][d]

// ---------------- PTX helpers (baseline sm_80+ features only) --------------
__device__ __forceinline__ uint32_t smem_u32(const void* p) {
    uint32_t a;
    asm("{ .reg .u64 t; cvta.to.shared.u64 t, %1; cvt.u32.u64 %0, t; }"
        : "=r"(a) : "l"(p));
    return a;
}
__device__ __forceinline__ void cp16(uint32_t dst, const void* src) {
    asm volatile("cp.async.cg.shared.global [%0], [%1], 16;"
                 :: "r"(dst), "l"(src));
}
__device__ __forceinline__ void cp_commit() {
    asm volatile("cp.async.commit_group;");
}
__device__ __forceinline__ void cp_wait0() {
    asm volatile("cp.async.wait_group 0;");
}
__device__ __forceinline__ void cp_wait1() {
    asm volatile("cp.async.wait_group 1;");
}
__device__ __forceinline__ void cp_wait2() {
    asm volatile("cp.async.wait_group 2;");
}
__device__ __forceinline__ void ldsm_x4(uint32_t r[4], uint32_t addr) {
    asm volatile("ldmatrix.sync.aligned.m8n8.x4.shared.b16 {%0,%1,%2,%3}, [%4];"
                 : "=r"(r[0]), "=r"(r[1]), "=r"(r[2]), "=r"(r[3]) : "r"(addr));
}
__device__ __forceinline__ void ldsm_x4_t(uint32_t r[4], uint32_t addr) {
    asm volatile("ldmatrix.sync.aligned.m8n8.x4.trans.shared.b16 {%0,%1,%2,%3}, [%4];"
                 : "=r"(r[0]), "=r"(r[1]), "=r"(r[2]), "=r"(r[3]) : "r"(addr));
}
__device__ __forceinline__ void mma_f16(float c[4], const uint32_t a[4],
                                        const uint32_t b0, const uint32_t b1) {
    asm volatile("mma.sync.aligned.m16n8k16.row.col.f32.f16.f16.f32 "
                 "{%0,%1,%2,%3}, {%4,%5,%6,%7}, {%8,%9}, {%0,%1,%2,%3};"
                 : "+f"(c[0]), "+f"(c[1]), "+f"(c[2]), "+f"(c[3])
                 : "r"(a[0]), "r"(a[1]), "r"(a[2]), "r"(a[3]),
                   "r"(b0), "r"(b1));
}
__device__ __forceinline__ uint32_t pack_h(float hi, float lo) {
    uint32_t d;
    asm("cvt.rn.f16x2.f32 %0, %1, %2;" : "=r"(d) : "f"(hi), "f"(lo));
    return d;
}
__device__ __forceinline__ float ex2(float x) {
    float y;
    asm("ex2.approx.f32 %0, %1;" : "=f"(y) : "f"(x));
    return y;
}

// swizzle for 128B rows (8 chunks of 16B)
#define SWZ(r, c) ((uint32_t)((r) * 128 + ((((c) ^ ((r) & 7))) << 4)))

// ---------------------------------------------------------------------------
// Prep 1: convert q/k/v activations to single fp16
// ---------------------------------------------------------------------------
__global__ __launch_bounds__(256)
void conv_act_kernel(const float* __restrict__ q, const float* __restrict__ k,
                     const float* __restrict__ v)
{
    const int z = blockIdx.y;
    const float* src = (z == 0) ? q : (z == 1 ? k : v);
    __half* hi = g_Ah[z];
    int idx = blockIdx.x * 256 + threadIdx.x;
    float4 x = ((const float4*)src)[idx];
    __half2 p0, p1;
    p0.x = __float2half(x.x); p0.y = __float2half(x.y);
    p1.x = __float2half(x.z); p1.y = __float2half(x.w);
    ((__half2*)hi)[idx*2]   = p0;
    ((__half2*)hi)[idx*2+1] = p1;
}

// ---------------------------------------------------------------------------
// Prep 2: W -> W^T single fp16 (tiled 32x32)
// ---------------------------------------------------------------------------
__global__ __launch_bounds__(256)
void conv_w_kernel(const float* __restrict__ Wq, const float* __restrict__ Wk,
                   const float* __restrict__ Wv)
{
    const int z = blockIdx.z;
    const float* W = (z == 0) ? Wq : (z == 1 ? Wk : Wv);
    __shared__ float t[32][33];
    const int tx = threadIdx.x & 31;
    const int ty = threadIdx.x >> 5;
    const int kb = blockIdx.y * 32;
    const int nb = blockIdx.x * 32;
    #pragma unroll
    for (int j = 0; j < 4; j++) {
        int kk = ty + j * 8;
        t[kk][tx] = W[(size_t)(kb + kk) * EMB + nb + tx];
    }
    __syncthreads();
    #pragma unroll
    for (int j = 0; j < 4; j++) {
        int nn = ty + j * 8;
        g_Wh[z][(size_t)(nb + nn) * EMB + kb + tx] = __float2half(t[tx][nn]);
    }
}

// ---------------------------------------------------------------------------
// Projection GEMM (R15 winner, unchanged): single-term fp16, D = Ah*Bh.
// CTA 128x128, 8 warps (64x32 each), 3-stage ring (48KB), 2 CTAs/SM.
// ---------------------------------------------------------------------------
#define STAGE_BYTES 16384
#define PROJ_SMEM   (3*STAGE_BYTES)
#define BOFF        8192

__device__ __forceinline__ uint32_t sw_off4(int row, int chunk) {
    return (uint32_t)(row * 64 + ((chunk ^ ((row >> 1) & 3)) << 4));
}

__device__ __forceinline__ void stage_chunk(
    const __half* __restrict__ Ah, const __half* __restrict__ Bh,
    int m0, int n0, int kc, uint32_t sbuf, int tid)
{
    #pragma unroll
    for (int i = 0; i < 2; i++) {
        int q = tid + i * 256;             // 0..511
        int r = q >> 2;                    // 0..127
        int c = q & 3;
        uint32_t off = sw_off4(r, c);
        size_t ga = (size_t)(m0 + r) * EMB + kc + c * 8;
        size_t gb = (size_t)(n0 + r) * EMB + kc + c * 8;
        cp16(sbuf +        off, Ah + ga);
        cp16(sbuf + BOFF + off, Bh + gb);
    }
}

__global__ __launch_bounds__(256, 2)
void proj_mma_kernel(const float* __restrict__ bq, const float* __restrict__ bk,
                     const float* __restrict__ bv)
{
    extern __shared__ char smem[];
    const int tid = threadIdx.x;
    const int wid = tid >> 5;
    const int lid = tid & 31;
    const int z   = blockIdx.z;
    const int m0  = blockIdx.y * 128;
    const int n0  = blockIdx.x * 128;
    const int wm  = wid & 1;
    const int wn  = wid >> 1;

    const __half* Ah = g_Ah[z];
    const __half* Bh = g_Wh[z];
    const float* bias = (z == 0) ? bq : (z == 1 ? bk : bv);

    const uint32_t sbase = smem_u32(smem);

    float acc[4][4][4];
    #pragma unroll
    for (int i = 0; i < 4; i++)
        #pragma unroll
        for (int j = 0; j < 4; j++)
            #pragma unroll
            for (int e = 0; e < 4; e++) acc[i][j][e] = 0.f;

    const int a_row = (lid & 7) + ((lid >> 3) & 1) * 8;
    const int a_csel = (lid >> 4) & 1;
    const int b_row = (lid & 7) + ((lid >> 4) & 1) * 8;
    const int b_csel = (lid >> 3) & 1;

    stage_chunk(Ah, Bh, m0, n0, 0, sbase, tid);
    cp_commit();
    stage_chunk(Ah, Bh, m0, n0, 32, sbase + STAGE_BYTES, tid);
    cp_commit();

    int rd = 0, st = 2;
    for (int it = 0; it < NIT; it++) {
        cp_wait1();
        __syncthreads();
        if (it + 2 < NIT)
            stage_chunk(Ah, Bh, m0, n0, (it + 2) * 32,
                        sbase + (uint32_t)st * STAGE_BYTES, tid);
        cp_commit();
        const uint32_t buf = sbase + (uint32_t)rd * STAGE_BYTES;

        #pragma unroll
        for (int ks = 0; ks < 2; ks++) {
            uint32_t ah[4][4];
            #pragma unroll
            for (int mt = 0; mt < 4; mt++) {
                int row = wm * 64 + mt * 16 + a_row;
                int c   = ks * 2 + a_csel;
                uint32_t off = sw_off4(row, c);
                ldsm_x4(ah[mt], buf + off);
            }
            #pragma unroll
            for (int np = 0; np < 2; np++) {
                int row = wn * 32 + np * 16 + b_row;
                int c   = ks * 2 + b_csel;
                uint32_t off = sw_off4(row, c);
                uint32_t rh[4];
                ldsm_x4(rh, buf + BOFF + off);
                #pragma unroll
                for (int mt = 0; mt < 4; mt++) {
                    mma_f16(acc[mt][np*2],   ah[mt], rh[0], rh[1]);
                    mma_f16(acc[mt][np*2+1], ah[mt], rh[2], rh[3]);
                }
            }
        }
        rd = (rd == 2) ? 0 : rd + 1;
        st = (st == 2) ? 0 : st + 1;
    }
    cp_wait0();

    // epilogue: all outputs single fp16; Q scaled by 0.125*log2e
    const float scl = (z == 0) ? 0.125f * 1.4426950408889634f : 1.0f;
    __half* C = (z == 0) ? g_Qh : (z == 1 ? g_Kh : g_Vh);
    #pragma unroll
    for (int mt = 0; mt < 4; mt++) {
        int r0 = m0 + wm * 64 + mt * 16 + (lid >> 2);
        #pragma unroll
        for (int nt = 0; nt < 4; nt++) {
            int col = n0 + wn * 32 + nt * 8 + (lid & 3) * 2;
            float b0v = bias[col], b1v = bias[col + 1];
            __half2 h2;
            h2.x = __float2half((acc[mt][nt][0] + b0v) * scl);
            h2.y = __float2half((acc[mt][nt][1] + b1v) * scl);
            *(__half2*)&C[(size_t)r0 * EMB + col] = h2;
            h2.x = __float2half((acc[mt][nt][2] + b0v) * scl);
            h2.y = __float2half((acc[mt][nt][3] + b1v) * scl);
            *(__half2*)&C[(size_t)(r0 + 8) * EMB + col] = h2;
        }
    }
}

// ---------------------------------------------------------------------------
// Tensor-core causal flash attention, R16: fully single-fp16, QTILE=64,
// 128 threads, 3-stage KV ring + 8KB Q park = 56KB/CTA ->
// 4 CTAs/SM (smem 224<=228, regs 4*128*128=64k) with FULL per-warp ILP.
// Ring ordering (proj-validated WAR-safe): wait1 -> sync -> stage(kb+2) ->
// commit -> compute buf[kb%3].
// ---------------------------------------------------------------------------
#define ABUF      16384
#define ATTN_SMEM (3*ABUF + 8192)

__device__ __forceinline__ void stage_kv(
    const __half* __restrict__ Kh, const __half* __restrict__ Vh,
    int k0, uint32_t buf, int tid)
{
    #pragma unroll
    for (int i = 0; i < 4; i++) {
        int u = tid + i * ATHREADS;     // 0..511
        int r = u >> 3;                 // row 0..63 (= kk)
        int c = u & 7;                  // 16B chunk (8 d)
        uint32_t off = SWZ(r, c);
        cp16(buf +        off, Kh + (size_t)(k0 + r) * HD + c * 8);
        cp16(buf + 8192 + off, Vh + (size_t)(k0 + r) * HD + c * 8);
    }
}

__global__ __launch_bounds__(ATHREADS)
void attn_mma_kernel(float* __restrict__ out)
{
    extern __shared__ char smem[];
    const int tid = threadIdx.x;
    const int wid = tid >> 5;                          // 0..3
    const int lid = tid & 31;
    const int bh  = blockIdx.y;
    const int qt  = (SEQ / QTILE) - 1 - blockIdx.x;    // long CTAs first
    const int q0  = qt * QTILE;
    const int nkb = qt + 1;                            // key blocks 0..qt

    const size_t slab = (size_t)bh * SEQ * HD;
    const __half* Qh = g_Qh + slab;
    const __half* Kh = g_Kh + slab;
    const __half* Vh = g_Vh + slab;
    float* O = out + slab;

    const uint32_t sb = smem_u32(smem);
    const int arow = (lid & 7) + ((lid >> 3) & 1) * 8;
    const int acs  = (lid >> 4) & 1;
    const int brow = (lid & 7) + ((lid >> 4) & 1) * 8;
    const int bcs  = (lid >> 3) & 1;
    const int vrow = ((lid >> 3) & 1) * 8 + (lid & 7);  // for ldsm.trans on V
    const int vcs  = (lid >> 4) & 1;

    // ---- prologue: Q -> park (sb+3*ABUF), KV0 -> buf0, KV1 -> buf1 ----
    const uint32_t qbuf = sb + 3u * ABUF;
    #pragma unroll
    for (int i = 0; i < 4; i++) {
        int u = tid + i * ATHREADS;     // 0..511
        int r = u >> 3;                 // 0..63
        int c = u & 7;
        uint32_t off = SWZ(r, c);
        cp16(qbuf + off, Qh + (size_t)(q0 + r) * HD + c * 8);
    }
    cp_commit();                                    // group: Q
    stage_kv(Kh, Vh, 0, sb, tid);
    cp_commit();                                    // group: KV0
    if (nkb > 1) stage_kv(Kh, Vh, KTILE, sb + ABUF, tid);
    cp_commit();                                    // group: KV1 (maybe empty)
    cp_wait2();                                     // Q complete
    __syncthreads();

    uint32_t qfh[4][4];
    #pragma unroll
    for (int s = 0; s < 4; s++) {
        uint32_t off = SWZ(wid * 16 + arow, 2 * s + acs);
        ldsm_x4(qfh[s], qbuf + off);
    }

    float oacc[8][4];
    #pragma unroll
    for (int j = 0; j < 8; j++)
        #pragma unroll
        for (int e = 0; e < 4; e++) oacc[j][e] = 0.f;
    float l0s = 0.f, l1s = 0.f;         // lane-local softmax denominators

    int rd = 0, st = 2;                 // ring indices: kb%3, (kb+2)%3
    for (int kb = 0; kb < nkb; kb++) {
        cp_wait1();                     // KV(kb) complete
        __syncthreads();                // all warps done reading buf `st`
        if (kb + 2 < nkb)
            stage_kv(Kh, Vh, (kb + 2) * KTILE,
                     sb + (uint32_t)st * ABUF, tid);
        cp_commit();                    // possibly empty: keeps group count
        const uint32_t bK = sb + (uint32_t)rd * ABUF;

        // ---- S = Qh @ Kh^T (1 MMA per tile) ----
        float sacc[8][4];
        #pragma unroll
        for (int j = 0; j < 8; j++)
            #pragma unroll
            for (int e = 0; e < 4; e++) sacc[j][e] = 0.f;

        #pragma unroll
        for (int s = 0; s < 4; s++) {
            uint32_t kh[8][2], r4[4];
            #pragma unroll
            for (int np = 0; np < 4; np++) {
                uint32_t off = SWZ(np * 16 + brow, 2 * s + bcs);
                ldsm_x4(r4, bK + off);
                kh[np*2][0]   = r4[0]; kh[np*2][1]   = r4[1];
                kh[np*2+1][0] = r4[2]; kh[np*2+1][1] = r4[3];
            }
            #pragma unroll
            for (int j = 0; j < 8; j++)
                mma_f16(sacc[j], qfh[s], kh[j][0], kh[j][1]);
        }

        // ---- causal mask (diagonal key block only) ----
        if (kb >= qt) {
            int rbase = q0 + wid * 16 + (lid >> 2);
            int cbase = kb * KTILE + (lid & 3) * 2;
            #pragma unroll
            for (int j = 0; j < 8; j++)
                #pragma unroll
                for (int e = 0; e < 2; e++) {
                    int cg = cbase + j * 8 + e;
                    if (cg > rbase)     sacc[j][e]     = -1e30f;
                    if (cg > rbase + 8) sacc[j][2 + e] = -1e30f;
                }
        }

        // ---- fused softmax (exp2) + fp16 pack + PV MMA (1 MMA/tile) ----
        #pragma unroll
        for (int s = 0; s < 4; s++) {
            int j0 = 2 * s, j1 = 2 * s + 1;
            float p00 = ex2(sacc[j0][0]), p01 = ex2(sacc[j0][1]);
            float p02 = ex2(sacc[j0][2]), p03 = ex2(sacc[j0][3]);
            float p10 = ex2(sacc[j1][0]), p11 = ex2(sacc[j1][1]);
            float p12 = ex2(sacc[j1][2]), p13 = ex2(sacc[j1][3]);
            l0s += p00 + p01 + p10 + p11;
            l1s += p02 + p03 + p12 + p13;

            uint32_t ph[4];
            ph[0] = pack_h(p01, p00);
            ph[1] = pack_h(p03, p02);
            ph[2] = pack_h(p11, p10);
            ph[3] = pack_h(p13, p12);

            uint32_t vh[8][2], r4[4];
            #pragma unroll
            for (int np = 0; np < 4; np++) {
                uint32_t off = SWZ(s * 16 + vrow, np * 2 + vcs);
                ldsm_x4_t(r4, bK + 8192 + off);
                vh[np*2][0]   = r4[0]; vh[np*2][1]   = r4[1];
                vh[np*2+1][0] = r4[2]; vh[np*2+1][1] = r4[3];
            }
            #pragma unroll
            for (int j = 0; j < 8; j++)
                mma_f16(oacc[j], ph, vh[j][0], vh[j][1]);
        }
        rd = (rd == 2) ? 0 : rd + 1;
        st = (st == 2) ? 0 : st + 1;
    }
    cp_wait0();

    // ---- epilogue: reduce l across the 4 quad lanes, normalize, store ----
    l0s += __shfl_xor_sync(0xffffffffu, l0s, 1);
    l0s += __shfl_xor_sync(0xffffffffu, l0s, 2);
    l1s += __shfl_xor_sync(0xffffffffu, l1s, 1);
    l1s += __shfl_xor_sync(0xffffffffu, l1s, 2);
    float inv0 = 1.f / l0s, inv1 = 1.f / l1s;
    int r = q0 + wid * 16 + (lid >> 2);
    #pragma unroll
    for (int j = 0; j < 8; j++) {
        int col = j * 8 + (lid & 3) * 2;
        float2 v0 = make_float2(oacc[j][0] * inv0, oacc[j][1] * inv0);
        float2 v1 = make_float2(oacc[j][2] * inv1, oacc[j][3] * inv1);
        *(float2*)&O[(size_t)r * HD + col]       = v0;
        *(float2*)&O[(size_t)(r + 8) * HD + col] = v1;
    }
}

// ---------------------------------------------------------------------------
extern "C" void kernel_launch(void* const* d_in, const int* in_sizes, int n_in,
                              void* d_out, int out_size)
{
    (void)in_sizes; (void)n_in; (void)out_size;
    const float* q  = (const float*)d_in[0];
    const float* k  = (const float*)d_in[1];
    const float* v  = (const float*)d_in[2];
    const float* Wq = (const float*)d_in[3];
    const float* bq = (const float*)d_in[4];
    const float* Wk = (const float*)d_in[5];
    const float* bk = (const float*)d_in[6];
    const float* Wv = (const float*)d_in[7];
    const float* bv = (const float*)d_in[8];
    float* out = (float*)d_out;

    cudaFuncSetAttribute(proj_mma_kernel,
                         cudaFuncAttributeMaxDynamicSharedMemorySize, PROJ_SMEM);
    cudaFuncSetAttribute(attn_mma_kernel,
                         cudaFuncAttributeMaxDynamicSharedMemorySize, ATTN_SMEM);

    dim3 cgrid(MROWS * EMB / (4 * 256), 3);
    conv_act_kernel<<<cgrid, 256>>>(q, k, v);

    dim3 wgrid(EMB / 32, EMB / 32, 3);
    conv_w_kernel<<<wgrid, 256>>>(Wq, Wk, Wv);

    dim3 pgrid(EMB / 128, MROWS / 128, 3);          // 8 x 32 x 3
    proj_mma_kernel<<<pgrid, 256, PROJ_SMEM>>>(bq, bk, bv);

    dim3 agrid(SEQ / QTILE, NB * NH);               // 32 x 32
    attn_mma_kernel<<<agrid, ATHREADS, ATTN_SMEM>>>(out);
}

// round 17
// speedup vs baseline: 1.0548x; 1.0548x over previous
#include <cuda_runtime.h>
#include <cuda_bf16.h>
#include <cuda_fp16.h>
#include <math.h>
#include <stdint.h>

#define SEQ   2048
#define EMB   1024
#define NH    16
#define HD    64
#define NB    2
#define MROWS (NB*SEQ)   // 4096
#define NIT2  (EMB/64)   // proj k-chunks of 64
#define QTILE 64
#define KTILE 64
#define ATHREADS 128

// ---------------- static device scratch (allocation-free) ------------------
__device__ __half g_Ah[3][MROWS*EMB];          // activations single fp16 [m][k]
__device__ __half g_Wh[3][EMB*EMB];            // W^T single fp16 [n][k]

__device__ __half g_Qh[MROWS*EMB];             // Q (x0.125*log2e) single fp16
__device__ __half g_Kh[MROWS*EMB];             // K single fp16 [kk][d]
__device__ __half g_Vh[MROWS*EMB];             // V single fp16 [kk][d]

// ---------------- PTX helpers (baseline sm_80+ features only) --------------
__device__ __forceinline__ uint32_t smem_u32(const void* p) {
    uint32_t a;
    asm("{ .reg .u64 t; cvta.to.shared.u64 t, %1; cvt.u32.u64 %0, t; }"
        : "=r"(a) : "l"(p));
    return a;
}
__device__ __forceinline__ void cp16(uint32_t dst, const void* src) {
    asm volatile("cp.async.cg.shared.global [%0], [%1], 16;"
                 :: "r"(dst), "l"(src));
}
__device__ __forceinline__ void cp_commit() {
    asm volatile("cp.async.commit_group;");
}
__device__ __forceinline__ void cp_wait0() {
    asm volatile("cp.async.wait_group 0;");
}
__device__ __forceinline__ void cp_wait1() {
    asm volatile("cp.async.wait_group 1;");
}
__device__ __forceinline__ void cp_wait2() {
    asm volatile("cp.async.wait_group 2;");
}
__device__ __forceinline__ void ldsm_x4(uint32_t r[4], uint32_t addr) {
    asm volatile("ldmatrix.sync.aligned.m8n8.x4.shared.b16 {%0,%1,%2,%3}, [%4];"
                 : "=r"(r[0]), "=r"(r[1]), "=r"(r[2]), "=r"(r[3]) : "r"(addr));
}
__device__ __forceinline__ void ldsm_x4_t(uint32_t r[4], uint32_t addr) {
    asm volatile("ldmatrix.sync.aligned.m8n8.x4.trans.shared.b16 {%0,%1,%2,%3}, [%4];"
                 : "=r"(r[0]), "=r"(r[1]), "=r"(r[2]), "=r"(r[3]) : "r"(addr));
}
__device__ __forceinline__ void mma_f16(float c[4], const uint32_t a[4],
                                        const uint32_t b0, const uint32_t b1) {
    asm volatile("mma.sync.aligned.m16n8k16.row.col.f32.f16.f16.f32 "
                 "{%0,%1,%2,%3}, {%4,%5,%6,%7}, {%8,%9}, {%0,%1,%2,%3};"
                 : "+f"(c[0]), "+f"(c[1]), "+f"(c[2]), "+f"(c[3])
                 : "r"(a[0]), "r"(a[1]), "r"(a[2]), "r"(a[3]),
                   "r"(b0), "r"(b1));
}
__device__ __forceinline__ uint32_t pack_h(float hi, float lo) {
    uint32_t d;
    asm("cvt.rn.f16x2.f32 %0, %1, %2;" : "=r"(d) : "f"(hi), "f"(lo));
    return d;
}
__device__ __forceinline__ float ex2(float x) {
    float y;
    asm("ex2.approx.f32 %0, %1;" : "=f"(y) : "f"(x));
    return y;
}

// swizzle for 128B rows (8 chunks of 16B)
#define SWZ(r, c) ((uint32_t)((r) * 128 + ((((c) ^ ((r) & 7))) << 4)))

// ---------------------------------------------------------------------------
// Prep (merged): blocks [0, 12288) convert activations to fp16;
// blocks [12288, 15360) transpose+convert W. One launch instead of two.
// ---------------------------------------------------------------------------
#define ACT_BLOCKS (3 * (MROWS * EMB / (4 * 256)))   // 12288
#define W_BLOCKS   (3 * (EMB / 32) * (EMB / 32))     // 3072

__global__ __launch_bounds__(256)
void conv_all_kernel(const float* __restrict__ q, const float* __restrict__ k,
                     const float* __restrict__ v,
                     const float* __restrict__ Wq, const float* __restrict__ Wk,
                     const float* __restrict__ Wv)
{
    const int bid = blockIdx.x;
    if (bid < ACT_BLOCKS) {
        const int z     = bid / (ACT_BLOCKS / 3);
        const int inner = bid % (ACT_BLOCKS / 3);
        const float* src = (z == 0) ? q : (z == 1 ? k : v);
        __half* hi = g_Ah[z];
        int idx = inner * 256 + threadIdx.x;
        float4 x = ((const float4*)src)[idx];
        __half2 p0, p1;
        p0.x = __float2half(x.x); p0.y = __float2half(x.y);
        p1.x = __float2half(x.z); p1.y = __float2half(x.w);
        ((__half2*)hi)[idx*2]   = p0;
        ((__half2*)hi)[idx*2+1] = p1;
    } else {
        const int wb  = bid - ACT_BLOCKS;
        const int z   = wb / (W_BLOCKS / 3);
        const int rem = wb % (W_BLOCKS / 3);
        const int kb  = (rem / 32) * 32;
        const int nb  = (rem % 32) * 32;
        const float* W = (z == 0) ? Wq : (z == 1 ? Wk : Wv);
        __shared__ float t[32][33];
        const int tx = threadIdx.x & 31;
        const int ty = threadIdx.x >> 5;
        #pragma unroll
        for (int j = 0; j < 4; j++) {
            int kk = ty + j * 8;
            t[kk][tx] = W[(size_t)(kb + kk) * EMB + nb + tx];
        }
        __syncthreads();
        #pragma unroll
        for (int j = 0; j < 4; j++) {
            int nn = ty + j * 8;
            g_Wh[z][(size_t)(nb + nn) * EMB + kb + tx] = __float2half(t[tx][nn]);
        }
    }
}

// ---------------------------------------------------------------------------
// Projection GEMM, R17: single-term fp16, K-chunk 64 (half the barriers).
// CTA 128x128, 8 warps (64x32 each), 3-stage ring (96KB), 2 CTAs/SM.
// Stage (32KB): [A 16K][B 16K], 128B rows, SWZ (same as attn tiles).
// ---------------------------------------------------------------------------
#define PSTAGE    32768
#define PROJ_SMEM (3*PSTAGE)
#define PBOFF     16384

__device__ __forceinline__ void stage_chunk(
    const __half* __restrict__ Ah, const __half* __restrict__ Bh,
    int m0, int n0, int kc, uint32_t sbuf, int tid)
{
    #pragma unroll
    for (int i = 0; i < 4; i++) {
        int u = tid + i * 256;             // 0..1023
        int r = u >> 3;                    // 0..127
        int c = u & 7;                     // 16B chunk (8 fp16)
        uint32_t off = SWZ(r, c);
        cp16(sbuf +         off, Ah + (size_t)(m0 + r) * EMB + kc + c * 8);
        cp16(sbuf + PBOFF + off, Bh + (size_t)(n0 + r) * EMB + kc + c * 8);
    }
}

__global__ __launch_bounds__(256, 2)
void proj_mma_kernel(const float* __restrict__ bq, const float* __restrict__ bk,
                     const float* __restrict__ bv)
{
    extern __shared__ char smem[];
    const int tid = threadIdx.x;
    const int wid = tid >> 5;
    const int lid = tid & 31;
    const int z   = blockIdx.z;
    const int m0  = blockIdx.y * 128;
    const int n0  = blockIdx.x * 128;
    const int wm  = wid & 1;
    const int wn  = wid >> 1;

    const __half* Ah = g_Ah[z];
    const __half* Bh = g_Wh[z];
    const float* bias = (z == 0) ? bq : (z == 1 ? bk : bv);

    const uint32_t sbase = smem_u32(smem);

    float acc[4][4][4];
    #pragma unroll
    for (int i = 0; i < 4; i++)
        #pragma unroll
        for (int j = 0; j < 4; j++)
            #pragma unroll
            for (int e = 0; e < 4; e++) acc[i][j][e] = 0.f;

    const int a_row = (lid & 7) + ((lid >> 3) & 1) * 8;
    const int a_csel = (lid >> 4) & 1;
    const int b_row = (lid & 7) + ((lid >> 4) & 1) * 8;
    const int b_csel = (lid >> 3) & 1;

    stage_chunk(Ah, Bh, m0, n0, 0, sbase, tid);
    cp_commit();
    stage_chunk(Ah, Bh, m0, n0, 64, sbase + PSTAGE, tid);
    cp_commit();

    int rd = 0, st = 2;
    for (int it = 0; it < NIT2; it++) {
        cp_wait1();
        __syncthreads();
        if (it + 2 < NIT2)
            stage_chunk(Ah, Bh, m0, n0, (it + 2) * 64,
                        sbase + (uint32_t)st * PSTAGE, tid);
        cp_commit();
        const uint32_t buf = sbase + (uint32_t)rd * PSTAGE;

        #pragma unroll
        for (int ks = 0; ks < 4; ks++) {
            uint32_t ah[4][4];
            #pragma unroll
            for (int mt = 0; mt < 4; mt++) {
                int row = wm * 64 + mt * 16 + a_row;
                uint32_t off = SWZ(row, ks * 2 + a_csel);
                ldsm_x4(ah[mt], buf + off);
            }
            #pragma unroll
            for (int np = 0; np < 2; np++) {
                int row = wn * 32 + np * 16 + b_row;
                uint32_t off = SWZ(row, ks * 2 + b_csel);
                uint32_t rh[4];
                ldsm_x4(rh, buf + PBOFF + off);
                #pragma unroll
                for (int mt = 0; mt < 4; mt++) {
                    mma_f16(acc[mt][np*2],   ah[mt], rh[0], rh[1]);
                    mma_f16(acc[mt][np*2+1], ah[mt], rh[2], rh[3]);
                }
            }
        }
        rd = (rd == 2) ? 0 : rd + 1;
        st = (st == 2) ? 0 : st + 1;
    }
    cp_wait0();

    // epilogue: all outputs single fp16; Q scaled by 0.125*log2e
    const float scl = (z == 0) ? 0.125f * 1.4426950408889634f : 1.0f;
    __half* C = (z == 0) ? g_Qh : (z == 1 ? g_Kh : g_Vh);
    #pragma unroll
    for (int mt = 0; mt < 4; mt++) {
        int r0 = m0 + wm * 64 + mt * 16 + (lid >> 2);
        #pragma unroll
        for (int nt = 0; nt < 4; nt++) {
            int col = n0 + wn * 32 + nt * 8 + (lid & 3) * 2;
            float b0v = bias[col], b1v = bias[col + 1];
            __half2 h2;
            h2.x = __float2half((acc[mt][nt][0] + b0v) * scl);
            h2.y = __float2half((acc[mt][nt][1] + b1v) * scl);
            *(__half2*)&C[(size_t)r0 * EMB + col] = h2;
            h2.x = __float2half((acc[mt][nt][2] + b0v) * scl);
            h2.y = __float2half((acc[mt][nt][3] + b1v) * scl);
            *(__half2*)&C[(size_t)(r0 + 8) * EMB + col] = h2;
        }
    }
}

// ---------------------------------------------------------------------------
// Tensor-core causal flash attention (byte-identical R15 winner):
// fully single-fp16, QTILE=64, 128 threads, 4-buffer KV ring + 8KB Q park.
// ---------------------------------------------------------------------------
#define ABUF      16384
#define ATTN_SMEM (4*ABUF + 8192)

__device__ __forceinline__ void stage_kv(
    const __half* __restrict__ Kh, const __half* __restrict__ Vh,
    int k0, uint32_t buf, int tid)
{
    #pragma unroll
    for (int i = 0; i < 4; i++) {
        int u = tid + i * ATHREADS;     // 0..511
        int r = u >> 3;                 // row 0..63 (= kk)
        int c = u & 7;                  // 16B chunk (8 d)
        uint32_t off = SWZ(r, c);
        cp16(buf +        off, Kh + (size_t)(k0 + r) * HD + c * 8);
        cp16(buf + 8192 + off, Vh + (size_t)(k0 + r) * HD + c * 8);
    }
}

__global__ __launch_bounds__(ATHREADS)
void attn_mma_kernel(float* __restrict__ out)
{
    extern __shared__ char smem[];
    const int tid = threadIdx.x;
    const int wid = tid >> 5;                          // 0..3
    const int lid = tid & 31;
    const int bh  = blockIdx.y;
    const int qt  = (SEQ / QTILE) - 1 - blockIdx.x;    // long CTAs first
    const int q0  = qt * QTILE;
    const int nkb = qt + 1;                            // key blocks 0..qt

    const size_t slab = (size_t)bh * SEQ * HD;
    const __half* Qh = g_Qh + slab;
    const __half* Kh = g_Kh + slab;
    const __half* Vh = g_Vh + slab;
    float* O = out + slab;

    const uint32_t sb = smem_u32(smem);
    const int arow = (lid & 7) + ((lid >> 3) & 1) * 8;
    const int acs  = (lid >> 4) & 1;
    const int brow = (lid & 7) + ((lid >> 4) & 1) * 8;
    const int bcs  = (lid >> 3) & 1;
    const int vrow = ((lid >> 3) & 1) * 8 + (lid & 7);  // for ldsm.trans on V
    const int vcs  = (lid >> 4) & 1;

    // ---- prologue: Q -> park (sb+4*ABUF), KV0 -> buf0, KV1 -> buf1 ----
    const uint32_t qbuf = sb + 4u * ABUF;
    #pragma unroll
    for (int i = 0; i < 4; i++) {
        int u = tid + i * ATHREADS;     // 0..511
        int r = u >> 3;                 // 0..63
        int c = u & 7;
        uint32_t off = SWZ(r, c);
        cp16(qbuf + off, Qh + (size_t)(q0 + r) * HD + c * 8);
    }
    cp_commit();                                    // group: Q
    stage_kv(Kh, Vh, 0, sb, tid);
    cp_commit();                                    // group: KV0
    if (nkb > 1) stage_kv(Kh, Vh, KTILE, sb + ABUF, tid);
    cp_commit();                                    // group: KV1 (maybe empty)
    cp_wait2();                                     // Q complete
    __syncthreads();

    uint32_t qfh[4][4];
    #pragma unroll
    for (int s = 0; s < 4; s++) {
        uint32_t off = SWZ(wid * 16 + arow, 2 * s + acs);
        ldsm_x4(qfh[s], qbuf + off);
    }

    float oacc[8][4];
    #pragma unroll
    for (int j = 0; j < 8; j++)
        #pragma unroll
        for (int e = 0; e < 4; e++) oacc[j][e] = 0.f;
    float l0s = 0.f, l1s = 0.f;         // lane-local softmax denominators

    for (int kb = 0; kb < nkb; kb++) {
        if (kb + 2 < nkb)
            stage_kv(Kh, Vh, (kb + 2) * KTILE,
                     sb + (uint32_t)((kb + 2) & 3) * ABUF, tid);
        cp_commit();                 // possibly empty
        cp_wait2();                  // KV(kb) complete
        __syncthreads();
        const uint32_t bK = sb + (uint32_t)(kb & 3) * ABUF;

        // ---- S = Qh @ Kh^T (1 MMA per tile) ----
        float sacc[8][4];
        #pragma unroll
        for (int j = 0; j < 8; j++)
            #pragma unroll
            for (int e = 0; e < 4; e++) sacc[j][e] = 0.f;

        #pragma unroll
        for (int s = 0; s < 4; s++) {
            uint32_t kh[8][2], r4[4];
            #pragma unroll
            for (int np = 0; np < 4; np++) {
                uint32_t off = SWZ(np * 16 + brow, 2 * s + bcs);
                ldsm_x4(r4, bK + off);
                kh[np*2][0]   = r4[0]; kh[np*2][1]   = r4[1];
                kh[np*2+1][0] = r4[2]; kh[np*2+1][1] = r4[3];
            }
            #pragma unroll
            for (int j = 0; j < 8; j++)
                mma_f16(sacc[j], qfh[s], kh[j][0], kh[j][1]);
        }

        // ---- causal mask (diagonal key block only) ----
        if (kb >= qt) {
            int rbase = q0 + wid * 16 + (lid >> 2);
            int cbase = kb * KTILE + (lid & 3) * 2;
            #pragma unroll
            for (int j = 0; j < 8; j++)
                #pragma unroll
                for (int e = 0; e < 2; e++) {
                    int cg = cbase + j * 8 + e;
                    if (cg > rbase)     sacc[j][e]     = -1e30f;
                    if (cg > rbase + 8) sacc[j][2 + e] = -1e30f;
                }
        }

        // ---- fused softmax (exp2) + fp16 pack + PV MMA (1 MMA/tile) ----
        #pragma unroll
        for (int s = 0; s < 4; s++) {
            int j0 = 2 * s, j1 = 2 * s + 1;
            float p00 = ex2(sacc[j0][0]), p01 = ex2(sacc[j0][1]);
            float p02 = ex2(sacc[j0][2]), p03 = ex2(sacc[j0][3]);
            float p10 = ex2(sacc[j1][0]), p11 = ex2(sacc[j1][1]);
            float p12 = ex2(sacc[j1][2]), p13 = ex2(sacc[j1][3]);
            l0s += p00 + p01 + p10 + p11;
            l1s += p02 + p03 + p12 + p13;

            uint32_t ph[4];
            ph[0] = pack_h(p01, p00);
            ph[1] = pack_h(p03, p02);
            ph[2] = pack_h(p11, p10);
            ph[3] = pack_h(p13, p12);

            uint32_t vh[8][2], r4[4];
            #pragma unroll
            for (int np = 0; np < 4; np++) {
                uint32_t off = SWZ(s * 16 + vrow, np * 2 + vcs);
                ldsm_x4_t(r4, bK + 8192 + off);
                vh[np*2][0]   = r4[0]; vh[np*2][1]   = r4[1];
                vh[np*2+1][0] = r4[2]; vh[np*2+1][1] = r4[3];
            }
            #pragma unroll
            for (int j = 0; j < 8; j++)
                mma_f16(oacc[j], ph, vh[j][0], vh[j][1]);
        }
    }
    cp_wait0();

    // ---- epilogue: reduce l across the 4 quad lanes, normalize, store ----
    l0s += __shfl_xor_sync(0xffffffffu, l0s, 1);
    l0s += __shfl_xor_sync(0xffffffffu, l0s, 2);
    l1s += __shfl_xor_sync(0xffffffffu, l1s, 1);
    l1s += __shfl_xor_sync(0xffffffffu, l1s, 2);
    float inv0 = 1.f / l0s, inv1 = 1.f / l1s;
    int r = q0 + wid * 16 + (lid >> 2);
    #pragma unroll
    for (int j = 0; j < 8; j++) {
        int col = j * 8 + (lid & 3) * 2;
        float2 v0 = make_float2(oacc[j][0] * inv0, oacc[j][1] * inv0);
        float2 v1 = make_float2(oacc[j][2] * inv1, oacc[j][3] * inv1);
        *(float2*)&O[(size_t)r * HD + col]       = v0;
        *(float2*)&O[(size_t)(r + 8) * HD + col] = v1;
    }
}

// ---------------------------------------------------------------------------
extern "C" void kernel_launch(void* const* d_in, const int* in_sizes, int n_in,
                              void* d_out, int out_size)
{
    (void)in_sizes; (void)n_in; (void)out_size;
    const float* q  = (const float*)d_in[0];
    const float* k  = (const float*)d_in[1];
    const float* v  = (const float*)d_in[2];
    const float* Wq = (const float*)d_in[3];
    const float* bq = (const float*)d_in[4];
    const float* Wk = (const float*)d_in[5];
    const float* bk = (const float*)d_in[6];
    const float* Wv = (const float*)d_in[7];
    const float* bv = (const float*)d_in[8];
    float* out = (float*)d_out;

    cudaFuncSetAttribute(proj_mma_kernel,
                         cudaFuncAttributeMaxDynamicSharedMemorySize, PROJ_SMEM);
    cudaFuncSetAttribute(attn_mma_kernel,
                         cudaFuncAttributeMaxDynamicSharedMemorySize, ATTN_SMEM);

    conv_all_kernel<<<ACT_BLOCKS + W_BLOCKS, 256>>>(q, k, v, Wq, Wk, Wv);

    dim3 pgrid(EMB / 128, MROWS / 128, 3);          // 8 x 32 x 3
    proj_mma_kernel<<<pgrid, 256, PROJ_SMEM>>>(bq, bk, bv);

    dim3 agrid(SEQ / QTILE, NB * NH);               // 32 x 32
    attn_mma_kernel<<<agrid, ATHREADS, ATTN_SMEM>>>(out);
}